// round 12
// baseline (speedup 1.0000x reference)
#include <cuda_runtime.h>
#include <cuda_bf16.h>
#include <cstdint>

#define B 16
#define S 200
#define D 256
#define H 8
#define W 32
#define RS 0.17677669529663689f   // 1/sqrt(32)

// ---------------- scratch (no allocations allowed) ----------------
__device__ float g_q[B * S * D];
__device__ float g_k[B * S * D];
__device__ float g_v[B * S * D];

// ---------------- bf16 split helpers ----------------
// pack two f32 into bf16x2 (v0 -> low half, v1 -> high half), round-to-nearest
__device__ __forceinline__ uint32_t bf16x2_rn(float v0, float v1) {
    uint32_t r;
    asm("cvt.rn.bf16x2.f32 %0, %1, %2;" : "=r"(r) : "f"(v1), "f"(v0));
    return r;
}

// split pair (v0,v1) into hi bf16x2 and lo (residual) bf16x2
__device__ __forceinline__ void split_pair(float v0, float v1,
                                           uint32_t& h, uint32_t& l) {
    h = bf16x2_rn(v0, v1);
    float h0 = __uint_as_float(h << 16);           // f32 value of low-half bf16
    float h1 = __uint_as_float(h & 0xffff0000u);   // f32 value of high-half bf16
    l = bf16x2_rn(v0 - h0, v1 - h1);
}

__device__ __forceinline__ void mma_bf16(
    float& c0, float& c1, float& c2, float& c3,
    uint32_t a0, uint32_t a1, uint32_t a2, uint32_t a3,
    uint32_t b0, uint32_t b1)
{
    asm volatile(
        "mma.sync.aligned.m16n8k16.row.col.f32.bf16.bf16.f32 "
        "{%0,%1,%2,%3}, {%4,%5,%6,%7}, {%8,%9}, {%0,%1,%2,%3};"
        : "+f"(c0), "+f"(c1), "+f"(c2), "+f"(c3)
        : "r"(a0), "r"(a1), "r"(a2), "r"(a3), "r"(b0), "r"(b1));
}

// ---------------- kernel 1: bf16 3-pass compensated TC projection ----------------
// C = Ah*Bh + Al*Bh + Ah*Bl  (bf16 hi/lo; missing term Al*Bl ~ 2^-16/product).
// Splits computed once at tile load, stored in smem as bf16x2 (same bytes as f32).
#define PTM 64
#define PTN 32
#define PTK 32
#define PLDH 20   // u32 per row: 16 data + 4 pad (conflict-free fragment LDS)

__global__ __launch_bounds__(256) void proj_tc_kernel(
    const float* __restrict__ x,
    const float* __restrict__ Wq, const float* __restrict__ bq,
    const float* __restrict__ Wk, const float* __restrict__ bk,
    const float* __restrict__ Wv, const float* __restrict__ bv)
{
    __shared__ uint32_t sah[PTM][PLDH], sal[PTM][PLDH];   // x hi/lo bf16x2
    __shared__ uint32_t sbh[PTN][PLDH], sbl[PTN][PLDH];   // W hi/lo bf16x2

    const int tid  = threadIdx.x;
    const int lane = tid & 31;
    const int wid  = tid >> 5;
    const int m0   = blockIdx.x * PTM;
    const int mat  = blockIdx.y >> 3;             // 0=q,1=k,2=v
    const int nc0  = (blockIdx.y & 7) * PTN;      // col block within matrix

    const float* Wm   = (mat == 0) ? Wq : (mat == 1) ? Wk : Wv;
    const float* bias = (mat == 0) ? bq : (mat == 1) ? bk : bv;
    float* dst        = (mat == 0) ? g_q : (mat == 1) ? g_k : g_v;

    const int warp_m = wid & 3;      // 4 warps over M (16 rows each)
    const int warp_n = wid >> 2;     // 2 warps over N (16 cols each)
    const int wm0 = warp_m * 16;
    const int wn0 = warp_n * 16;

    const int g  = lane >> 2;        // groupID
    const int tg = lane & 3;         // thread-in-group

    // loader mappings
    const int xrow = tid >> 2;           // 0..63, 8 f32 each
    const int xk   = (tid & 3) * 8;      // f32 col base
    const int wrow = tid >> 3;           // 0..31, 4 f32 each
    const int wk   = (tid & 7) * 4;

    float c[2][4];
    #pragma unroll
    for (int j = 0; j < 2; j++)
        #pragma unroll
        for (int r = 0; r < 4; r++) c[j][r] = 0.f;

    #pragma unroll 1
    for (int t = 0; t < D / PTK; t++) {
        // issue global loads early (latency overlaps prior MMAs + barrier)
        float4 xa = *(const float4*)&x [(size_t)(m0  + xrow) * D + t * PTK + xk];
        float4 xb = *(const float4*)&x [(size_t)(m0  + xrow) * D + t * PTK + xk + 4];
        float4 wa = *(const float4*)&Wm[(size_t)(nc0 + wrow) * D + t * PTK + wk];

        __syncthreads();   // previous iteration's MMAs finished reading smem

        // split + store x: 8 f32 -> 4 hi u32 + 4 lo u32
        {
            uint32_t h[4], l[4];
            split_pair(xa.x, xa.y, h[0], l[0]);
            split_pair(xa.z, xa.w, h[1], l[1]);
            split_pair(xb.x, xb.y, h[2], l[2]);
            split_pair(xb.z, xb.w, h[3], l[3]);
            *(uint4*)&sah[xrow][xk >> 1] = make_uint4(h[0], h[1], h[2], h[3]);
            *(uint4*)&sal[xrow][xk >> 1] = make_uint4(l[0], l[1], l[2], l[3]);
        }
        // split + store W: 4 f32 -> 2 hi + 2 lo
        {
            uint32_t h0, h1, l0, l1;
            split_pair(wa.x, wa.y, h0, l0);
            split_pair(wa.z, wa.w, h1, l1);
            *(uint2*)&sbh[wrow][wk >> 1] = make_uint2(h0, h1);
            *(uint2*)&sbl[wrow][wk >> 1] = make_uint2(l0, l1);
        }
        __syncthreads();

        // 2 x k16 MMA steps per tile
        #pragma unroll
        for (int kk = 0; kk < 2; kk++) {
            const int base = kk * 8;
            const int rb = wm0 + g;
            uint32_t ah0 = sah[rb    ][base + tg];
            uint32_t ah1 = sah[rb + 8][base + tg];
            uint32_t ah2 = sah[rb    ][base + tg + 4];
            uint32_t ah3 = sah[rb + 8][base + tg + 4];
            uint32_t al0 = sal[rb    ][base + tg];
            uint32_t al1 = sal[rb + 8][base + tg];
            uint32_t al2 = sal[rb    ][base + tg + 4];
            uint32_t al3 = sal[rb + 8][base + tg + 4];

            #pragma unroll
            for (int j = 0; j < 2; j++) {
                const int cb = wn0 + 8 * j + g;
                uint32_t bh0 = sbh[cb][base + tg];
                uint32_t bh1 = sbh[cb][base + tg + 4];
                uint32_t bl0 = sbl[cb][base + tg];
                uint32_t bl1 = sbl[cb][base + tg + 4];

                mma_bf16(c[j][0], c[j][1], c[j][2], c[j][3],
                         ah0, ah1, ah2, ah3, bh0, bh1);
                mma_bf16(c[j][0], c[j][1], c[j][2], c[j][3],
                         al0, al1, al2, al3, bh0, bh1);
                mma_bf16(c[j][0], c[j][1], c[j][2], c[j][3],
                         ah0, ah1, ah2, ah3, bl0, bl1);
            }
        }
    }

    const int r0 = m0 + wm0 + g;
    #pragma unroll
    for (int j = 0; j < 2; j++) {
        const int cg = nc0 + wn0 + 8 * j + tg * 2;
        const float b0v = bias[cg], b1v = bias[cg + 1];
        float2 v0 = make_float2(c[j][0] + b0v, c[j][1] + b1v);
        float2 v1 = make_float2(c[j][2] + b0v, c[j][3] + b1v);
        *(float2*)&dst[(size_t)r0 * D + cg]       = v0;
        *(float2*)&dst[(size_t)(r0 + 8) * D + cg] = v1;
    }
}

// ---------------- kernel 2: fused attention, 128 threads/block (frozen best) ----------------
__global__ __launch_bounds__(128, 12) void fused_attn_kernel(
    const float* __restrict__ tK, const float* __restrict__ tV,
    const int* __restrict__ mask, float* __restrict__ out)
{
    __shared__ float sp[H][S];          // 6.4 KB
    __shared__ float4 pbuf[2][64];      // 2 KB

    const int bi = blockIdx.x;
    const int b  = bi / S;
    const int warp = threadIdx.x >> 5;  // 0..3
    const int lane = threadIdx.x & 31;

    // ---- Phase A ----
    {
        const float* qrow = g_q + (size_t)bi * D + lane * 8;
        const float4 qa = *(const float4*)(qrow);
        const float4 qb = *(const float4*)(qrow + 4);

        #pragma unroll 5
        for (int j = warp; j < S; j += 4) {
            const float* tp = tK  + ((size_t)bi * S + j) * D + lane * 8;
            const float* kp = g_k + ((size_t)(b * S + j)) * D + lane * 8;
            float4 t0 = __ldcs((const float4*)(tp));
            float4 t1 = __ldcs((const float4*)(tp + 4));
            float4 k0 = *(const float4*)(kp);
            float4 k1 = *(const float4*)(kp + 4);

            float p = qa.x * (t0.x + k0.x) + qa.y * (t0.y + k0.y)
                    + qa.z * (t0.z + k0.z) + qa.w * (t0.w + k0.w)
                    + qb.x * (t1.x + k1.x) + qb.y * (t1.y + k1.y)
                    + qb.z * (t1.z + k1.z) + qb.w * (t1.w + k1.w);

            p += __shfl_xor_sync(0xFFFFFFFFu, p, 1);
            p += __shfl_xor_sync(0xFFFFFFFFu, p, 2);
            if ((lane & 3) == 0) sp[lane >> 2][j] = p;
        }
    }
    __syncthreads();

    // ---- Phase B: warp handles heads warp and warp+4 ----
    #pragma unroll
    for (int hh = 0; hh < 2; hh++) {
        const int h = warp + hh * 4;
        float vals[7];
        float mx = -1e30f;
        #pragma unroll
        for (int t = 0; t < 7; t++) {
            int j = lane + t * 32;
            if (j < S) {
                float mb = 10000.0f * (1.0f - (float)mask[b * S + j]);
                vals[t] = sp[h][j] * RS + mb;
            } else {
                vals[t] = -1e30f;
            }
            mx = fmaxf(mx, vals[t]);
        }
        #pragma unroll
        for (int o = 16; o; o >>= 1) mx = fmaxf(mx, __shfl_xor_sync(0xFFFFFFFFu, mx, o));

        float sum = 0.f;
        #pragma unroll
        for (int t = 0; t < 7; t++) {
            vals[t] = __expf(vals[t] - mx);
            sum += vals[t];
        }
        #pragma unroll
        for (int o = 16; o; o >>= 1) sum += __shfl_xor_sync(0xFFFFFFFFu, sum, o);

        const float inv = 1.0f / sum;
        #pragma unroll
        for (int t = 0; t < 7; t++) {
            int j = lane + t * 32;
            if (j < S) sp[h][j] = vals[t] * inv;
        }
    }
    __syncthreads();

    // ---- Phase C ----
    {
        const int g = threadIdx.x >> 6;     // j-group 0..1
        const int l = threadIdx.x & 63;     // d-slice 0..63
        const int d = l * 4;
        const int h = l >> 3;

        const float* tvb = tV  + ((size_t)bi * S) * D + d;
        const float* vvb = g_v + ((size_t)b * S) * D + d;

        float4 acc = make_float4(0.f, 0.f, 0.f, 0.f);
        #pragma unroll 5
        for (int j = g; j < S; j += 2) {
            float4 tv = __ldcs((const float4*)(tvb + (size_t)j * D));
            float4 vv = *(const float4*)(vvb + (size_t)j * D);
            float pj = sp[h][j];
            acc.x += pj * (tv.x + vv.x);
            acc.y += pj * (tv.y + vv.y);
            acc.z += pj * (tv.z + vv.z);
            acc.w += pj * (tv.w + vv.w);
        }
        pbuf[g][l] = acc;
    }
    __syncthreads();

    if (threadIdx.x < 64) {
        const int l = threadIdx.x;
        float4 a0 = pbuf[0][l], a1 = pbuf[1][l];
        float4 r;
        r.x = a0.x + a1.x;
        r.y = a0.y + a1.y;
        r.z = a0.z + a1.z;
        r.w = a0.w + a1.w;
        *(float4*)(out + (size_t)bi * D + l * 4) = r;
    }
}

// ---------------- launch ----------------
extern "C" void kernel_launch(void* const* d_in, const int* in_sizes, int n_in,
                              void* d_out, int out_size)
{
    const float* x    = (const float*)d_in[0];
    const float* tK   = (const float*)d_in[1];
    const float* tV   = (const float*)d_in[2];
    const int*   mask = (const int*)  d_in[3];
    const float* Wq   = (const float*)d_in[4];
    const float* bq   = (const float*)d_in[5];
    const float* Wk   = (const float*)d_in[6];
    const float* bk   = (const float*)d_in[7];
    const float* Wv   = (const float*)d_in[8];
    const float* bv   = (const float*)d_in[9];
    float* out = (float*)d_out;

    dim3 pgrid(B * S / PTM, 24);   // 50 x (3 matrices * 8 col blocks) = 1200 blocks
    proj_tc_kernel<<<pgrid, 256>>>(x, Wq, bq, Wk, bk, Wv, bv);

    fused_attn_kernel<<<B * S, 128>>>(tK, tV, mask, out);
}